// round 5
// baseline (speedup 1.0000x reference)
#include <cuda_runtime.h>

// SoftNCutsLoss: H=W=D=16, P=4096, K=4, RADIUS=5, O_I=10, O_X=4, N=2, C=1.
//
// W[p,q] = mask(sqd<=25) * exp(-(I_p-I_q)^2/10) * exp(-sqd/4)   (symmetric)
// num_k = sum_pq W A_k[p] A_k[q];  den_k = sum_pq W A_k[q]
// out[n] = 4 - sum_k num_k/(den_k+1e-8)
//
// Half-space offset iteration (257 offsets) + diagonal handled analytically.
// Per-thread (p) accumulators: rs = sum w, s_k = sum w*A_k[q]
//   num_k(p) = 2*A_k[p]*s_k + [group0] A_k[p]^2
//   den_k(p) = A_k[p]*rs + s_k + [group0] A_k[p]
// All reduced to 16 global scalars via shuffle + smem + atomicAdd.

#define P_VOX   4096
#define K_LAB   4
#define NOFF_PAD 260     // 257 real half-space offsets + 3 dummies
#define NGROUP  4
#define GSIZE   65       // 260 / 4
#define SMEM_I_BYTES   16384
#define SMEM_A_BYTES   65536
#define SMEM_TAB_BYTES (NOFF_PAD * 16)
#define SMEM_RED_BYTES 256
#define SMEM_BYTES (SMEM_I_BYTES + SMEM_A_BYTES + SMEM_TAB_BYTES + SMEM_RED_BYTES)

__device__ int4  g_tab[NOFF_PAD];
__device__ float g_acc[16];   // [n][0..3]=num_k, [n][4..7]=den_k

// ---------------------------------------------------------------------------
// Init: zero accumulators, build half-space offset table. Deterministic.
// ---------------------------------------------------------------------------
__global__ void sncut_init_kernel() {
    if (threadIdx.x == 0) {
        const float LOG2E = 1.4426950408889634f;
        int cnt = 0;
        for (int dx = 0; dx <= 5; ++dx)
            for (int dy = -5; dy <= 5; ++dy)
                for (int dz = -5; dz <= 5; ++dz) {
                    int sq = dx*dx + dy*dy + dz*dz;
                    if (sq == 0 || sq > 25) continue;
                    bool pos = (dx > 0) || (dx == 0 && (dy > 0 || (dy == 0 && dz > 0)));
                    if (!pos) continue;
                    int4 e;
                    e.x = dx; e.y = dy; e.z = dz;
                    e.w = __float_as_int(-0.25f * LOG2E * (float)sq);
                    g_tab[cnt++] = e;
                }
        // cnt == 257; pad with always-invalid entries
        for (; cnt < NOFF_PAD; ++cnt) {
            int4 e; e.x = 100; e.y = 0; e.z = 0; e.w = 0;
            g_tab[cnt] = e;
        }
        #pragma unroll
        for (int i = 0; i < 16; ++i) g_acc[i] = 0.0f;
    }
}

// ---------------------------------------------------------------------------
// Main: grid (16 voxel-chunks, 2 n, 4 offset-groups), 256 threads.
// One thread per voxel. Whole per-n volume staged in shared memory.
// ---------------------------------------------------------------------------
__global__ __launch_bounds__(256)
void sncut_main_kernel(const float* __restrict__ labels,
                       const float* __restrict__ inputs) {
    extern __shared__ char smem[];
    float*  sI   = (float*)smem;
    float4* sA   = (float4*)(smem + SMEM_I_BYTES);
    int4*   sTab = (int4*)(smem + SMEM_I_BYTES + SMEM_A_BYTES);
    float*  sRed = (float*)(smem + SMEM_I_BYTES + SMEM_A_BYTES + SMEM_TAB_BYTES);

    const int tid = threadIdx.x;
    const int n   = blockIdx.y;
    const float* I = inputs + n * P_VOX;
    const float* A = labels + n * K_LAB * P_VOX;

    // Stage I (vectorized)
    const float4* I4  = (const float4*)I;
    float4*       sI4 = (float4*)sI;
    #pragma unroll
    for (int i = 0; i < 4; ++i)
        sI4[tid + i * 256] = I4[tid + i * 256];

    // Stage A with K-transpose: sA[p] = {A0[p],A1[p],A2[p],A3[p]}
    #pragma unroll
    for (int i = 0; i < 4; ++i) {
        int j = tid + i * 256;                       // float4 group: voxels 4j..4j+3
        float4 a0 = ((const float4*)(A + 0 * P_VOX))[j];
        float4 a1 = ((const float4*)(A + 1 * P_VOX))[j];
        float4 a2 = ((const float4*)(A + 2 * P_VOX))[j];
        float4 a3 = ((const float4*)(A + 3 * P_VOX))[j];
        sA[4*j + 0] = make_float4(a0.x, a1.x, a2.x, a3.x);
        sA[4*j + 1] = make_float4(a0.y, a1.y, a2.y, a3.y);
        sA[4*j + 2] = make_float4(a0.z, a1.z, a2.z, a3.z);
        sA[4*j + 3] = make_float4(a0.w, a1.w, a2.w, a3.w);
    }
    if (tid < NOFF_PAD) sTab[tid] = g_tab[tid];
    if (tid + 256 < NOFF_PAD) sTab[tid + 256] = g_tab[tid + 256];
    __syncthreads();

    const int p = (blockIdx.x << 8) + tid;
    const int z = p & 15, y = (p >> 4) & 15, x = p >> 8;
    const float  Ip = sI[p];
    const float4 Ap = sA[p];
    const float C2 = -0.14426950408889634f;  // -0.1 * log2(e)

    float rs = 0.f, s0 = 0.f, s1 = 0.f, s2 = 0.f, s3 = 0.f;
    const int base = blockIdx.z * GSIZE;

    #pragma unroll 5
    for (int o = 0; o < GSIZE; ++o) {
        int4 e = sTab[base + o];                  // uniform -> broadcast
        int qx = x + e.x, qy = y + e.y, qz = z + e.z;
        bool ok = ((unsigned)qx < 16u) & ((unsigned)qy < 16u) & ((unsigned)qz < 16u);
        int q = (qx << 8) + (qy << 4) + qz;
        q = ok ? q : 0;
        float d   = sI[q] - Ip;
        float arg = fmaf(d * d, C2, __int_as_float(e.w));
        arg = ok ? arg : -10000.0f;               // ex2(-1e4) == 0
        float w;
        asm("ex2.approx.f32 %0, %1;" : "=f"(w) : "f"(arg));
        float4 Aq = sA[q];
        rs += w;
        s0 = fmaf(w, Aq.x, s0);
        s1 = fmaf(w, Aq.y, s1);
        s2 = fmaf(w, Aq.z, s2);
        s3 = fmaf(w, Aq.w, s3);
    }

    // Finalize per-thread num/den contributions (diagonal only in group 0)
    const float cen = (blockIdx.z == 0) ? 1.0f : 0.0f;
    float v[8];
    v[0] = Ap.x * (2.f * s0 + cen * Ap.x);
    v[1] = Ap.y * (2.f * s1 + cen * Ap.y);
    v[2] = Ap.z * (2.f * s2 + cen * Ap.z);
    v[3] = Ap.w * (2.f * s3 + cen * Ap.w);
    v[4] = fmaf(Ap.x, rs, s0) + cen * Ap.x;
    v[5] = fmaf(Ap.y, rs, s1) + cen * Ap.y;
    v[6] = fmaf(Ap.z, rs, s2) + cen * Ap.z;
    v[7] = fmaf(Ap.w, rs, s3) + cen * Ap.w;

    // Warp reduce
    #pragma unroll
    for (int j = 0; j < 8; ++j) {
        #pragma unroll
        for (int off = 16; off; off >>= 1)
            v[j] += __shfl_down_sync(0xffffffffu, v[j], off);
    }
    const int wid = tid >> 5, lane = tid & 31;
    if (lane == 0) {
        #pragma unroll
        for (int j = 0; j < 8; ++j) sRed[wid * 8 + j] = v[j];
    }
    __syncthreads();
    if (tid < 8) {
        float acc = 0.f;
        #pragma unroll
        for (int w8 = 0; w8 < 8; ++w8) acc += sRed[w8 * 8 + tid];
        atomicAdd(&g_acc[n * 8 + tid], acc);
    }
}

// ---------------------------------------------------------------------------
// Final: out[n] = 4 - sum_k num_k/(den_k + 1e-8)
// ---------------------------------------------------------------------------
__global__ void sncut_final_kernel(float* __restrict__ out) {
    int n = threadIdx.x;
    if (n < 2) {
        float loss = 0.f;
        #pragma unroll
        for (int k = 0; k < K_LAB; ++k)
            loss += g_acc[n * 8 + k] / (g_acc[n * 8 + 4 + k] + 1e-8f);
        out[n] = 4.0f - loss;
    }
}

extern "C" void kernel_launch(void* const* d_in, const int* in_sizes, int n_in,
                              void* d_out, int out_size) {
    // Identify inputs by size: labels = 2*4*4096 = 32768, inputs = 2*1*4096 = 8192
    const float* labels;
    const float* inputs;
    if (in_sizes[0] == 2 * K_LAB * P_VOX) {
        labels = (const float*)d_in[0];
        inputs = (const float*)d_in[1];
    } else {
        labels = (const float*)d_in[1];
        inputs = (const float*)d_in[0];
    }
    float* out = (float*)d_out;

    cudaFuncSetAttribute(sncut_main_kernel,
                         cudaFuncAttributeMaxDynamicSharedMemorySize, SMEM_BYTES);

    sncut_init_kernel<<<1, 32>>>();
    dim3 grid(P_VOX / 256, 2, NGROUP);
    sncut_main_kernel<<<grid, 256, SMEM_BYTES>>>(labels, inputs);
    sncut_final_kernel<<<1, 32>>>(out);
}

// round 10
// speedup vs baseline: 1.1775x; 1.1775x over previous
#include <cuda_runtime.h>

// SoftNCutsLoss: H=W=D=16, P=4096, K=4, RADIUS=5, O_I=10, O_X=4, N=2, C=1.
//
// W[p,q] = mask(sqd<=25) * exp(-(I_p-I_q)^2/10) * exp(-sqd/4)   (symmetric)
// num_k = sum_pq W A_k[p] A_k[q];  den_k = sum_pq W A_k[q]
// out[n] = 4 - sum_k num_k/(den_k+1e-8)
//
// Single-kernel design:
//  * 257 half-space offsets in __constant__ memory, built at COMPILE time
//    (constexpr) -- no init kernel.
//  * grid (16 voxel-chunks, 2 n, 4 offset-groups) = 128 blocks; per-thread
//    accumulators rs = sum w, s_k = sum w*A_k[q]; diagonal added in group 0.
//  * per-block 8 partials -> g_part (overwritten each run, no zeroing),
//    threadfence + atomicInc-wrap last-block pattern folds the final
//    reduction into the same launch (self-resetting, graph-replay safe).

#define P_VOX    4096
#define K_LAB    4
#define NOFF_PAD 260          // 257 real half-space offsets + 3 dummies
#define NGROUP   4
#define GSIZE    65           // 260 / 4
#define NBLK_X   16
#define NBATCH   2
#define TOTAL_BLOCKS (NBLK_X * NBATCH * NGROUP)   // 128

#define SMEM_I_BYTES 16384
#define SMEM_A_BYTES 65536
#define SMEM_BYTES   (SMEM_I_BYTES + SMEM_A_BYTES + 256)

// ---------------------------------------------------------------------------
// Compile-time half-space offset table (x,y,z step + precomputed spatial
// log2-weight c = -sqd/4 * log2(e)).
// ---------------------------------------------------------------------------
struct TabT {
    int   x[NOFF_PAD], y[NOFF_PAD], z[NOFF_PAD];
    float c[NOFF_PAD];
};

constexpr TabT gen_tab() {
    TabT t{};
    int cnt = 0;
    for (int dx = 0; dx <= 5; ++dx)
        for (int dy = -5; dy <= 5; ++dy)
            for (int dz = -5; dz <= 5; ++dz) {
                int sq = dx*dx + dy*dy + dz*dz;
                if (sq == 0 || sq > 25) continue;
                bool pos = (dx > 0) || (dx == 0 && (dy > 0 || (dy == 0 && dz > 0)));
                if (!pos) continue;
                t.x[cnt] = dx; t.y[cnt] = dy; t.z[cnt] = dz;
                t.c[cnt] = -0.25f * 1.4426950408889634f * (float)sq;
                ++cnt;
            }
    for (; cnt < NOFF_PAD; ++cnt) {     // pad: always out-of-bounds
        t.x[cnt] = 100; t.y[cnt] = 0; t.z[cnt] = 0; t.c[cnt] = 0.0f;
    }
    return t;
}

constexpr TabT h_tab = gen_tab();
__constant__ TabT c_tab = h_tab;

__device__ float    g_part[TOTAL_BLOCKS * 8];  // overwritten every run
__device__ unsigned g_ctr;                     // atomicInc wraps -> self-reset

// ---------------------------------------------------------------------------
__global__ __launch_bounds__(256)
void sncut_kernel(const float* __restrict__ labels,
                  const float* __restrict__ inputs,
                  float* __restrict__ out) {
    extern __shared__ char smem[];
    float*  sI   = (float*)smem;
    float4* sA   = (float4*)(smem + SMEM_I_BYTES);
    float*  sRed = (float*)(smem + SMEM_I_BYTES + SMEM_A_BYTES);
    __shared__ bool isLast;

    const int tid = threadIdx.x;
    const int n   = blockIdx.y;
    const float* I = inputs + n * P_VOX;
    const float* A = labels + n * K_LAB * P_VOX;

    // Stage I (vectorized)
    const float4* I4  = (const float4*)I;
    float4*       sI4 = (float4*)sI;
    #pragma unroll
    for (int i = 0; i < 4; ++i)
        sI4[tid + i * 256] = I4[tid + i * 256];

    // Stage A with K-transpose: sA[p] = {A0[p],A1[p],A2[p],A3[p]}
    #pragma unroll
    for (int i = 0; i < 4; ++i) {
        int j = tid + i * 256;                       // float4 group: voxels 4j..4j+3
        float4 a0 = ((const float4*)(A + 0 * P_VOX))[j];
        float4 a1 = ((const float4*)(A + 1 * P_VOX))[j];
        float4 a2 = ((const float4*)(A + 2 * P_VOX))[j];
        float4 a3 = ((const float4*)(A + 3 * P_VOX))[j];
        sA[4*j + 0] = make_float4(a0.x, a1.x, a2.x, a3.x);
        sA[4*j + 1] = make_float4(a0.y, a1.y, a2.y, a3.y);
        sA[4*j + 2] = make_float4(a0.z, a1.z, a2.z, a3.z);
        sA[4*j + 3] = make_float4(a0.w, a1.w, a2.w, a3.w);
    }
    __syncthreads();

    const int p = (blockIdx.x << 8) + tid;
    const int z = p & 15, y = (p >> 4) & 15, x = p >> 8;
    const float  Ip = sI[p];
    const float4 Ap = sA[p];
    const float C2 = -0.14426950408889634f;  // -0.1 * log2(e)

    float rs = 0.f, s0 = 0.f, s1 = 0.f, s2 = 0.f, s3 = 0.f;
    const int base = blockIdx.z * GSIZE;

    #pragma unroll 5
    for (int o = 0; o < GSIZE; ++o) {
        int qx = x + c_tab.x[base + o];              // uniform LDC
        int qy = y + c_tab.y[base + o];
        int qz = z + c_tab.z[base + o];
        bool ok = ((unsigned)(qx | qy | qz) < 16u);  // exact for 0..15 ranges
        int q = (qx << 8) + (qy << 4) + qz;
        q = ok ? q : 0;
        float d   = sI[q] - Ip;
        float arg = fmaf(d * d, C2, c_tab.c[base + o]);
        arg = ok ? arg : -10000.0f;                  // ex2(-1e4) == 0
        float w;
        asm("ex2.approx.f32 %0, %1;" : "=f"(w) : "f"(arg));
        float4 Aq = sA[q];
        rs += w;
        s0 = fmaf(w, Aq.x, s0);
        s1 = fmaf(w, Aq.y, s1);
        s2 = fmaf(w, Aq.z, s2);
        s3 = fmaf(w, Aq.w, s3);
    }

    // Per-thread num/den contributions (diagonal only in group 0)
    const float cen = (blockIdx.z == 0) ? 1.0f : 0.0f;
    float v[8];
    v[0] = Ap.x * (2.f * s0 + cen * Ap.x);
    v[1] = Ap.y * (2.f * s1 + cen * Ap.y);
    v[2] = Ap.z * (2.f * s2 + cen * Ap.z);
    v[3] = Ap.w * (2.f * s3 + cen * Ap.w);
    v[4] = fmaf(Ap.x, rs, s0) + cen * Ap.x;
    v[5] = fmaf(Ap.y, rs, s1) + cen * Ap.y;
    v[6] = fmaf(Ap.z, rs, s2) + cen * Ap.z;
    v[7] = fmaf(Ap.w, rs, s3) + cen * Ap.w;

    // Warp reduce -> smem -> block partial
    #pragma unroll
    for (int j = 0; j < 8; ++j) {
        #pragma unroll
        for (int off = 16; off; off >>= 1)
            v[j] += __shfl_down_sync(0xffffffffu, v[j], off);
    }
    const int wid = tid >> 5, lane = tid & 31;
    if (lane == 0) {
        #pragma unroll
        for (int j = 0; j < 8; ++j) sRed[wid * 8 + j] = v[j];
    }
    __syncthreads();

    const int bid = (blockIdx.z * NBATCH + blockIdx.y) * NBLK_X + blockIdx.x;
    if (tid < 8) {
        float acc = 0.f;
        #pragma unroll
        for (int w8 = 0; w8 < 8; ++w8) acc += sRed[w8 * 8 + tid];
        g_part[bid * 8 + tid] = acc;
        __threadfence();                 // make partial device-visible
    }
    __syncthreads();

    // Last-block-done: atomicInc wraps to 0 at TOTAL_BLOCKS-1 -> self-resetting
    if (tid == 0) {
        unsigned old = atomicInc(&g_ctr, TOTAL_BLOCKS - 1);
        isLast = (old == TOTAL_BLOCKS - 1);
    }
    __syncthreads();

    if (isLast) {
        if (tid < 16) {
            int nn = tid >> 3, j = tid & 7;
            float acc = 0.f;
            #pragma unroll
            for (int gz = 0; gz < NGROUP; ++gz)
                #pragma unroll
                for (int gx = 0; gx < NBLK_X; ++gx)
                    acc += __ldcg(&g_part[((gz * NBATCH + nn) * NBLK_X + gx) * 8 + j]);
            sRed[64 + tid] = acc;
        }
        __syncthreads();
        if (tid < 2) {
            float loss = 0.f;
            #pragma unroll
            for (int k = 0; k < K_LAB; ++k)
                loss += sRed[64 + tid * 8 + k] / (sRed[64 + tid * 8 + 4 + k] + 1e-8f);
            out[tid] = 4.0f - loss;
        }
    }
}

// ---------------------------------------------------------------------------
extern "C" void kernel_launch(void* const* d_in, const int* in_sizes, int n_in,
                              void* d_out, int out_size) {
    // labels = 2*4*4096 = 32768 elems, inputs = 2*1*4096 = 8192 elems
    const float* labels;
    const float* inputs;
    if (in_sizes[0] == 2 * K_LAB * P_VOX) {
        labels = (const float*)d_in[0];
        inputs = (const float*)d_in[1];
    } else {
        labels = (const float*)d_in[1];
        inputs = (const float*)d_in[0];
    }
    float* out = (float*)d_out;

    cudaFuncSetAttribute(sncut_kernel,
                         cudaFuncAttributeMaxDynamicSharedMemorySize, SMEM_BYTES);

    dim3 grid(NBLK_X, NBATCH, NGROUP);
    sncut_kernel<<<grid, 256, SMEM_BYTES>>>(labels, inputs, out);
}